// round 6
// baseline (speedup 1.0000x reference)
#include <cuda_runtime.h>
#include <cstdint>

// CTRNN scan: register weights, dual-k f32x2 packing, and two-phase batch
// groups so the DSMEM exchange latency hides behind the other group's step.
// B=64, T=4096, F=128, H=512, O=10, DT=0.1, fp32.
//
// 16 clusters x 8 CTAs, 4 batches/cluster split into groups G0={b0,b1},
// G1={b2,b3}. Per step: phase(G0) computes + publishes G0's next state
// (1x 512B bulk copy per peer), then phase(G1) runs while G0's copies fly.
// State layout [g][buf][rank][b][64k] keeps slices contiguous and lets the
// mainloop read same-batch k-quads via one LDS.128 per 2 fma.rn.f32x2.

#define T_STEPS   4096
#define F_IN      128
#define H_DIM     512
#define O_OUT     10
#define CLUSTER_N 8
#define NCOL      64
#define NTHREADS  512
#define GRID      128
#define DT_C      0.1f
#define SLICE_BYTES 512u    // 64 cols x 2 batches x 4B

typedef unsigned long long ull;

struct __align__(16) Smem {
    float  s[2][3][CLUSTER_N][2][NCOL]; // [g][buf][rank][b][kk]  24KB
    double part[2][2][8 * NCOL];        // [g][ping][kq*64+h] = {p_b0,p_b1}
    float  xbuf[2][2][2][F_IN];         // [g][ping][b][f]
    ull    mbar[2][3][CLUSTER_N];       // [g][buf][source rank]
};

__device__ __forceinline__ uint32_t smem_u32(const void* p) {
    uint32_t a;
    asm("{ .reg .u64 t; cvta.to.shared.u64 t, %1; cvt.u32.u64 %0, t; }"
        : "=r"(a) : "l"(p));
    return a;
}
__device__ __forceinline__ ull fma2(ull a, ull b, ull c) {
    ull d;
    asm("fma.rn.f32x2 %0, %1, %2, %3;" : "=l"(d) : "l"(a), "l"(b), "l"(c));
    return d;
}
__device__ __forceinline__ ull packxy(float x, float y) {
    ull d;
    asm("mov.b64 %0, {%1, %2};" : "=l"(d) : "f"(x), "f"(y));
    return d;
}
__device__ __forceinline__ void unpack2(ull v, float& x, float& y) {
    asm("mov.b64 {%0, %1}, %2;" : "=f"(x), "=f"(y) : "l"(v));
}
__device__ __forceinline__ float tanh_fast(float x) {
    float y;
    asm("tanh.approx.f32 %0, %1;" : "=f"(y) : "f"(x));
    return y;
}
__device__ __forceinline__ void mbar_wait(uint32_t m, uint32_t ph) {
    uint32_t done;
    asm volatile(
        "{\n\t.reg .pred p;\n\t"
        "mbarrier.try_wait.parity.acquire.cta.shared::cta.b64 p, [%1], %2;\n\t"
        "selp.b32 %0, 1, 0, p;\n\t}"
        : "=r"(done) : "r"(m), "r"(ph) : "memory");
    while (!done) {
        asm volatile(
            "{\n\t.reg .pred p;\n\t"
            "mbarrier.try_wait.parity.acquire.cta.shared::cta.b64 p, [%1], %2, 0x40;\n\t"
            "selp.b32 %0, 1, 0, p;\n\t}"
            : "=r"(done) : "r"(m), "r"(ph) : "memory");
    }
}
__device__ __forceinline__ void mbar_expect(uint32_t m, uint32_t bytes) {
    asm volatile("mbarrier.arrive.expect_tx.shared::cta.b64 _, [%0], %1;"
                 :: "r"(m), "r"(bytes) : "memory");
}
__device__ __forceinline__ void mbar_arrive(uint32_t m) {
    asm volatile("mbarrier.arrive.shared::cta.b64 _, [%0];"
                 :: "r"(m) : "memory");
}
__device__ __forceinline__ uint32_t mapa_u32(uint32_t la, uint32_t r) {
    uint32_t ra;
    asm("mapa.shared::cluster.u32 %0, %1, %2;" : "=r"(ra) : "r"(la), "r"(r));
    return ra;
}
__device__ __forceinline__ void bulk_copy_peer(uint32_t dst, uint32_t src,
                                               uint32_t bytes, uint32_t rmbar) {
    asm volatile(
        "cp.async.bulk.shared::cluster.shared::cta.mbarrier::complete_tx::bytes "
        "[%0], [%1], %2, [%3];"
        :: "r"(dst), "r"(src), "r"(bytes), "r"(rmbar) : "memory");
}

__global__ void __cluster_dims__(CLUSTER_N, 1, 1) __launch_bounds__(NTHREADS, 1)
ctrnn_scan(const float* __restrict__ xg,   const float* __restrict__ ic,
           const float* __restrict__ Wing, const float* __restrict__ Wrecg,
           const float* __restrict__ bg,   const float* __restrict__ taug,
           const float* __restrict__ Rw,   const float* __restrict__ Rb,
           float* __restrict__ outg)
{
    __shared__ Smem sm;

    uint32_t rank;
    asm("mov.u32 %0, %%cluster_ctarank;" : "=r"(rank));
    const int tid = threadIdx.x;
    const int cl  = blockIdx.x / CLUSTER_N;
    const int c0  = (int)rank * NCOL;
    const int gb0 = cl * 4;

    const int h  = tid & 63;    // column within slice
    const int kq = tid >> 6;    // K eighth == source rank this warp-pair consumes

    // ---- weights to registers, dual-k packed {w_k, w_k+1} ----
    ull wr[32];
    #pragma unroll
    for (int j = 0; j < 32; j++)
        wr[j] = packxy(Wrecg[(kq * 64 + 2 * j) * H_DIM + c0 + h],
                       Wrecg[(kq * 64 + 2 * j + 1) * H_DIM + c0 + h]);
    ull wi[8];
    #pragma unroll
    for (int j = 0; j < 8; j++)
        wi[j] = packxy(Wing[(kq * 16 + 2 * j) * H_DIM + c0 + h],
                       Wing[(kq * 16 + 2 * j + 1) * H_DIM + c0 + h]);

    // ---- epilogue-thread params & register state (tid<128) ----
    const int eh = tid & 63, bb = (tid >> 6) & 1;
    float biasv = 0.f, arv = 0.f, sreg[2] = {0.f, 0.f};
    if (tid < 128) {
        biasv = bg[c0 + eh];
        arv   = DT_C / taug[c0 + eh];
        sreg[0] = sreg[1] = ic[c0 + eh];
    }

    // ---- init: state buffer 0 (both groups, full), x[0], mbarriers ----
    for (int i = tid; i < 2 * CLUSTER_N * 2 * NCOL; i += NTHREADS) {
        const int g = i >> 10, rem = i & 1023;
        const int r = rem >> 7, b = (rem >> 6) & 1, kk = rem & 63;
        sm.s[g][0][r][b][kk] = ic[r * 64 + kk];
    }
    {
        const int g = tid >> 8, b = (tid >> 7) & 1, f = tid & 127;
        sm.xbuf[g][0][b][f] = xg[(ull)(gb0 + g * 2 + b) * T_STEPS * F_IN + f];
    }
    const uint32_t mbase = smem_u32(&sm.mbar[0][0][0]);
    const uint32_t sbase = smem_u32(&sm.s[0][0][0][0][0]);
    if (tid == 0) {
        for (int i = 0; i < 2 * 3 * CLUSTER_N; i++) {
            asm volatile("mbarrier.init.shared::cta.b64 [%0], %1;"
                         :: "r"(mbase + i * 8u), "r"(1) : "memory");
        }
        for (int g = 0; g < 2; g++)
            for (int n = 0; n < 3; n++)
                for (int r = 0; r < CLUSTER_N; r++)
                    if (r != (int)rank)
                        mbar_expect(mbase + (uint32_t)(((g * 3 + n) * 8 + r)) * 8u,
                                    SLICE_BYTES);
    }
    __syncthreads();
    asm volatile("barrier.cluster.arrive.aligned;" ::: "memory");
    asm volatile("barrier.cluster.wait.aligned;"   ::: "memory");

    for (int t = 0; t < T_STEPS; t++) {
        const int cur  = t % 3;
        const int nbuf = (t + 1) % 3;
        const int cx   = t & 1;
        const uint32_t par = (((uint32_t)t - 1u) / 3u) & 1u;
        float px = 0.f;

        #pragma unroll
        for (int g = 0; g < 2; g++) {
            // wait for this warp-pair's source slice of group g
            if (t > 0) {
                const uint32_t m = mbase
                    + (uint32_t)((g * 3 + cur) * 8 + kq) * 8u;
                mbar_wait(m, par);
                if ((tid & 63) == 0 && kq != (int)rank)
                    mbar_expect(m, SLICE_BYTES);    // re-arm for step t+3
            }

            // x prefetch issued once, early in phase 0
            if (g == 0 && t + 1 < T_STEPS)
                px = xg[((ull)(gb0 + (tid >> 7)) * T_STEPS + (t + 1)) * F_IN
                        + (tid & 127)];

            // ---- mainloop: dual-k f32x2, 2 batches, zero packing movs ----
            const double2* __restrict__ s0 =
                (const double2*)&sm.s[g][cur][kq][0][0];
            const double2* __restrict__ s1 =
                (const double2*)&sm.s[g][cur][kq][1][0];
            ull a0 = 0ull, a1 = 0ull;
            #pragma unroll
            for (int j = 0; j < 16; j++) {
                const double2 v0 = s0[j], v1 = s1[j];
                a0 = fma2(wr[2 * j],     __double_as_longlong(v0.x), a0);
                a0 = fma2(wr[2 * j + 1], __double_as_longlong(v0.y), a0);
                a1 = fma2(wr[2 * j],     __double_as_longlong(v1.x), a1);
                a1 = fma2(wr[2 * j + 1], __double_as_longlong(v1.y), a1);
            }
            const double2* __restrict__ x0 =
                (const double2*)&sm.xbuf[g][cx][0][0];
            const double2* __restrict__ x1 =
                (const double2*)&sm.xbuf[g][cx][1][0];
            #pragma unroll
            for (int j = 0; j < 4; j++) {
                const double2 v0 = x0[kq * 4 + j], v1 = x1[kq * 4 + j];
                a0 = fma2(wi[2 * j],     __double_as_longlong(v0.x), a0);
                a0 = fma2(wi[2 * j + 1], __double_as_longlong(v0.y), a0);
                a1 = fma2(wi[2 * j],     __double_as_longlong(v1.x), a1);
                a1 = fma2(wi[2 * j + 1], __double_as_longlong(v1.y), a1);
            }
            float l0, h0, l1, h1;
            unpack2(a0, l0, h0);
            unpack2(a1, l1, h1);
            sm.part[g][cx][kq * 64 + h] =
                __longlong_as_double(packxy(l0 + h0, l1 + h1));

            // stage x[t+1] during phase 0
            if (g == 0 && t + 1 < T_STEPS)
                sm.xbuf[tid >> 8][cx ^ 1][(tid >> 7) & 1][tid & 127] = px;

            __syncthreads();    // partials (+ staged x) visible

            // ---- epilogue: reduce 8 kq, tanh, update, publish slice ----
            if (tid < 128) {
                const float* __restrict__ pp =
                    (const float*)&sm.part[g][cx][0];
                float sum = 0.f;
                #pragma unroll
                for (int q = 0; q < 8; q++)
                    sum += pp[(q * 64 + eh) * 2 + bb];
                const float ns =
                    fmaf(arv, tanh_fast(sum + biasv) - sreg[g], sreg[g]);
                sreg[g] = ns;
                sm.s[g][nbuf][rank][bb][eh] = ns;

                asm volatile("bar.sync 1, 128;" ::: "memory");

                const uint32_t off = (uint32_t)((g * 3 + nbuf) * 8 + (int)rank);
                if (tid < 7) {
                    asm volatile("fence.proxy.async.shared::cta;" ::: "memory");
                    const uint32_t peer = (uint32_t)tid
                                        + ((uint32_t)tid >= rank ? 1u : 0u);
                    const uint32_t src = sbase + off * 512u;
                    const uint32_t rmb = mbase + off * 8u;
                    bulk_copy_peer(mapa_u32(src, peer), src, SLICE_BYTES,
                                   mapa_u32(rmb, peer));
                } else if (tid == 7) {
                    mbar_arrive(mbase + off * 8u);  // local release
                }
            }
        }
    }

    // ---- final waits: both groups' buffer T%3 slices, then readout ----
    const uint32_t fpar = (((uint32_t)T_STEPS - 1u) / 3u) & 1u;
    #pragma unroll
    for (int g = 0; g < 2; g++)
        mbar_wait(mbase + (uint32_t)((g * 3 + (T_STEPS % 3)) * 8 + kq) * 8u,
                  fpar);
    __syncthreads();

    if (rank == 0) {
        const int wid = tid >> 5, lane = tid & 31;
        for (int bo = wid; bo < 4 * O_OUT; bo += NTHREADS / 32) {
            const int b = bo / O_OUT, o = bo % O_OUT;
            float acc = 0.f;
            for (int k = lane; k < H_DIM; k += 32)
                acc += sm.s[b >> 1][T_STEPS % 3][k >> 6][b & 1][k & 63]
                     * Rw[k * O_OUT + o];
            #pragma unroll
            for (int off = 16; off; off >>= 1)
                acc += __shfl_xor_sync(0xffffffffu, acc, off);
            if (lane == 0) outg[(gb0 + b) * O_OUT + o] = acc + Rb[o];
        }
    }

    // exit safety: no CTA leaves while peer copies may still target its SMEM
    asm volatile("barrier.cluster.arrive.aligned;" ::: "memory");
    asm volatile("barrier.cluster.wait.aligned;"   ::: "memory");
}

extern "C" void kernel_launch(void* const* d_in, const int* in_sizes, int n_in,
                              void* d_out, int out_size)
{
    const float* x    = (const float*)d_in[0];
    const float* ic   = (const float*)d_in[1];
    const float* Win  = (const float*)d_in[2];
    const float* Wrec = (const float*)d_in[3];
    const float* b    = (const float*)d_in[4];
    const float* tau  = (const float*)d_in[5];
    const float* Rw   = (const float*)d_in[6];
    const float* Rb   = (const float*)d_in[7];
    float* out = (float*)d_out;
    (void)in_sizes; (void)n_in; (void)out_size;

    ctrnn_scan<<<GRID, NTHREADS>>>(x, ic, Win, Wrec, b, tau, Rw, Rb, out);
}